// round 16
// baseline (speedup 1.0000x reference)
#include <cuda_runtime.h>
#include <cuda_fp16.h>
#include <math.h>
#include <stdint.h>

// ---------------------------------------------------------------------------
// Problem constants
// ---------------------------------------------------------------------------
#define B       1024
#define D       512
#define C       100000
#define TM      128                    // CTA tile rows
#define TN      128                    // CTA tile classes
#define NT      ((C + TN - 1) / TN)    // 782 class tiles
#define NTE     (NT * 2)               // 2 col-half partials per class tile
#define NTILES  (8 * NT)               // 6256 total tiles (8 row x 782 class)
#define GRIDP   296                    // persistent CTAs (148 SM x 2)
#define KCHUNK  64                     // fp16 K elems per chunk (128B rows)
#define NCHUNK  (D / KCHUNK)           // 8 chunks per tile
#define SCALE_F 64.0f
#define L2E_64  92.33248261689366f     // 64 * log2(e)

// ArcFace margin constants (margin = 0.5)
#define COS_M  0.8775825618903728f
#define SIN_M  0.47942553860420301f
#define TH_M  (-0.8775825618903728f)
#define MM_M   0.23971276930210151f

// smem: per stage A tile 128x128B (16KB) + B tile 128x128B (16KB)
#define TILE_BYTES  16384
#define STAGE_BYTES (2 * TILE_BYTES)
#define SMEM_BYTES  (3 * STAGE_BYTES)      // 98304 -> 2 CTA/SM

// Scratch (__device__ globals; no allocations allowed).
// g_winv padded to NT*TN; zero-initialized, pad never written -> OOB classes
// read winv == 0 and contribute exp(-64) ~ 0 to the partial sums.
__device__ __half g_Eh[(size_t)B * D];
__device__ __half g_Wh[(size_t)C * D];
__device__ float  g_einv[B];
__device__ float  g_winv[NT * TN];
__device__ float  g_psum[(size_t)B * NTE];
__device__ float  g_nll[B];

// ---------------------------------------------------------------------------
// PTX helpers (base ISA only -- nothing gated on sm_103a)
// ---------------------------------------------------------------------------
__device__ __forceinline__ uint32_t smem_u32(const void* p) {
    uint32_t a;
    asm("{ .reg .u64 t; cvta.to.shared.u64 t, %1; cvt.u32.u64 %0, t; }"
        : "=r"(a) : "l"(p));
    return a;
}
__device__ __forceinline__ void cp16(uint32_t dst, const void* src) {
    asm volatile("cp.async.cg.shared.global [%0], [%1], 16;"
                 :: "r"(dst), "l"(src));
}
__device__ __forceinline__ void cp_commit() {
    asm volatile("cp.async.commit_group;" ::: "memory");
}
template <int N> __device__ __forceinline__ void cp_wait() {
    asm volatile("cp.async.wait_group %0;" :: "n"(N) : "memory");
}
__device__ __forceinline__ void st_zero16(uint32_t dst) {
    asm volatile("st.shared.v4.u32 [%0], {%1, %1, %1, %1};"
                 :: "r"(dst), "r"(0u) : "memory");
}
__device__ __forceinline__ void ldsm4(uint32_t* r, uint32_t addr) {
    asm volatile("ldmatrix.sync.aligned.m8n8.x4.shared.b16 {%0,%1,%2,%3}, [%4];"
                 : "=r"(r[0]), "=r"(r[1]), "=r"(r[2]), "=r"(r[3]) : "r"(addr));
}
__device__ __forceinline__ void mma_f16(float* d, const uint32_t* a,
                                        const uint32_t* b) {
    asm volatile(
        "mma.sync.aligned.m16n8k16.row.col.f32.f16.f16.f32 "
        "{%0,%1,%2,%3}, {%4,%5,%6,%7}, {%8,%9}, {%0,%1,%2,%3};"
        : "+f"(d[0]), "+f"(d[1]), "+f"(d[2]), "+f"(d[3])
        : "r"(a[0]), "r"(a[1]), "r"(a[2]), "r"(a[3]), "r"(b[0]), "r"(b[1]));
}
__device__ __forceinline__ float ex2(float x) {
    float r;
    asm("ex2.approx.ftz.f32 %0, %1;" : "=f"(r) : "f"(x));
    return r;
}

// ---------------------------------------------------------------------------
// Norm + fp16-convert kernels (one warp per row, single fused pass)
// ---------------------------------------------------------------------------
__global__ void e_conv_kernel(const float* __restrict__ E) {
    int warp = (blockIdx.x * blockDim.x + threadIdx.x) >> 5;
    int lane = threadIdx.x & 31;
    if (warp >= B) return;
    const float* row = E + (size_t)warp * D;
    __half2* dst = (__half2*)(g_Eh + (size_t)warp * D);
    float ss = 0.f;
    #pragma unroll
    for (int j = 0; j < 4; j++) {
        float4 v = *(const float4*)(row + (j * 32 + lane) * 4);
        ss = fmaf(v.x, v.x, fmaf(v.y, v.y, fmaf(v.z, v.z, fmaf(v.w, v.w, ss))));
        dst[(j * 32 + lane) * 2]     = __floats2half2_rn(v.x, v.y);
        dst[(j * 32 + lane) * 2 + 1] = __floats2half2_rn(v.z, v.w);
    }
    #pragma unroll
    for (int o = 16; o > 0; o >>= 1) ss += __shfl_xor_sync(0xffffffffu, ss, o);
    if (lane == 0) g_einv[warp] = 1.0f / fmaxf(sqrtf(ss), 1e-12f);
}

__global__ void w_conv_kernel(const float* __restrict__ W) {
    int warp = (blockIdx.x * blockDim.x + threadIdx.x) >> 5;
    int lane = threadIdx.x & 31;
    if (warp >= C) return;
    const float* row = W + (size_t)warp * D;
    __half2* dst = (__half2*)(g_Wh + (size_t)warp * D);
    float ss = 0.f;
    #pragma unroll
    for (int j = 0; j < 4; j++) {
        float4 v = *(const float4*)(row + (j * 32 + lane) * 4);
        ss = fmaf(v.x, v.x, fmaf(v.y, v.y, fmaf(v.z, v.z, fmaf(v.w, v.w, ss))));
        dst[(j * 32 + lane) * 2]     = __floats2half2_rn(v.x, v.y);
        dst[(j * 32 + lane) * 2 + 1] = __floats2half2_rn(v.z, v.w);
    }
    #pragma unroll
    for (int o = 16; o > 0; o >>= 1) ss += __shfl_xor_sync(0xffffffffu, ss, o);
    if (lane == 0) g_winv[warp] = 1.0f / fmaxf(sqrtf(ss), 1e-12f);
}

// ---------------------------------------------------------------------------
// Main: persistent-CTA fp16 mma.sync GEMM, restructured so the hot path is
// compile-time unrolled: outer runtime loop over this CTA's tiles, inner
// UNROLLED loop over the 8 chunks. Stage base addresses live in a 3-entry
// register array rotated by 2 per tile (8 mod 3), so all smem offsets are
// immediates. Next tile's chunks 0,1 are issued from chunk slots 6,7 ->
// the cp.async pipeline never drains at tile boundaries; the epilogue runs
// while those loads are in flight. Fixed-max softmax partials (max == 64).
// ---------------------------------------------------------------------------
__global__ void __launch_bounds__(256, 2)
gemm_tc_kernel(void) {
    extern __shared__ char sdata[];

    const int tid  = threadIdx.x;
    const int wid  = tid >> 5;
    const int lane = tid & 31;
    const int wm   = wid >> 1;         // 0..3 : 32-row slice
    const int wn   = wid & 1;          // 0..1 : 64-col half
    const int qid  = lane >> 2;        // 0..7
    const int ql   = lane & 3;         // 0..3
    const int bid  = blockIdx.x;

    const int ntile = (NTILES - bid + GRIDP - 1) / GRIDP;

    const uint32_t s0 = smem_u32(sdata);
    uint32_t pst[3] = { s0, s0 + STAGE_BYTES, s0 + 2 * STAGE_BYTES };

    // loader thread mapping (shared by all issues)
    const int lr = tid >> 3;           // 0..31 base row (stride 32)
    const int lc = tid & 7;            // 16B column 0..7

    // issue one chunk's loads: A 16KB + B 16KB, XOR-swizzled, then commit
    auto issue = [&](int rowBase, int classBase, int kof, uint32_t sa) {
        const uint32_t sb = sa + TILE_BYTES;
        const __half*  Ep = g_Eh + (size_t)rowBase * D + kof;
        #pragma unroll
        for (int i = 0; i < 4; i++) {
            int r = lr + i * 32;
            uint32_t dst = sa + r * 128 + ((lc ^ (r & 7)) << 4);
            cp16(dst, Ep + (size_t)r * D + lc * 8);
        }
        #pragma unroll
        for (int i = 0; i < 4; i++) {
            int r = lr + i * 32;
            int cls = classBase + r;
            uint32_t dst = sb + r * 128 + ((lc ^ (r & 7)) << 4);
            if (cls < C) cp16(dst, g_Wh + (size_t)cls * D + kof + lc * 8);
            else         st_zero16(dst);
        }
        cp_commit();
    };

    // ldmatrix per-lane address components
    const int aRow = (lane & 7) + ((lane >> 3) & 1) * 8;   // row within 16
    const int kgA  = lane >> 4;                            // k half
    const int bRow = (lane & 7) + (lane >> 4) * 8;         // row within 16
    const int kgB  = (lane >> 3) & 1;

    float acc[2][8][4];
    #pragma unroll
    for (int mt = 0; mt < 2; mt++)
        #pragma unroll
        for (int nt = 0; nt < 8; nt++)
            #pragma unroll
            for (int c = 0; c < 4; c++) acc[mt][nt][c] = 0.f;

    // prologue: first tile's chunks 0,1
    {
        const int tile0 = bid;
        issue((tile0 & 7) * TM, (tile0 >> 3) * TN, 0 * KCHUNK, pst[0]);
        issue((tile0 & 7) * TM, (tile0 >> 3) * TN, 1 * KCHUNK, pst[1]);
    }

    for (int t = 0; t < ntile; t++) {
        const int  tile      = bid + t * GRIDP;
        const int  rowBase   = (tile & 7) * TM;
        const int  classBase = (tile >> 3) * TN;
        const bool lastTile  = (t == ntile - 1);
        const int  ntile2    = tile + GRIDP;              // next tile index
        const int  nrb       = (ntile2 & 7) * TM;
        const int  ncb       = (ntile2 >> 3) * TN;

        #pragma unroll
        for (int k = 0; k < NCHUNK; k++) {
            if (k == NCHUNK - 1) {
                if (lastTile) cp_wait<0>();
                else          cp_wait<1>();
            } else {
                cp_wait<1>();
            }
            __syncthreads();

            // issue chunk k+2 of the stream (stage index (k+2)%3 is
            // compile-time under the current rotation)
            if (k < NCHUNK - 2) {
                issue(rowBase, classBase, (k + 2) * KCHUNK, pst[(k + 2) % 3]);
            } else if (!lastTile) {
                issue(nrb, ncb, (k + 2 - NCHUNK) * KCHUNK, pst[(k + 2) % 3]);
            } else {
                cp_commit();           // empty: keep wait counts uniform
            }

            // compute chunk k from stage pst[k%3]
            {
                const uint32_t sa = pst[k % 3];
                const uint32_t sb = sa + TILE_BYTES;
                #pragma unroll
                for (int ks = 0; ks < 4; ks++) {
                    uint32_t a[2][4], bb[4][4];
                    const int cA = ks * 2 + kgA;
                    const int cB = ks * 2 + kgB;
                    const uint32_t swA = (uint32_t)((cA ^ (lane & 7)) << 4);
                    const uint32_t swB = (uint32_t)((cB ^ (lane & 7)) << 4);
                    #pragma unroll
                    for (int mt = 0; mt < 2; mt++)
                        ldsm4(a[mt], sa + (wm * 32 + mt * 16 + aRow) * 128 + swA);
                    #pragma unroll
                    for (int ntp = 0; ntp < 4; ntp++)
                        ldsm4(bb[ntp], sb + (wn * 64 + ntp * 16 + bRow) * 128 + swB);
                    #pragma unroll
                    for (int mt = 0; mt < 2; mt++)
                        #pragma unroll
                        for (int nt = 0; nt < 8; nt++) {
                            uint32_t bfrag[2] = { bb[nt >> 1][(nt & 1) * 2],
                                                  bb[nt >> 1][(nt & 1) * 2 + 1] };
                            mma_f16(acc[mt][nt], a[mt], bfrag);
                        }
                }
            }
        }

        // ---- tile epilogue (next tile's chunks 0,1 already in flight) ----
        {
            const int tileIdx = (tile >> 3) * 2 + wn;
            float wv[16];
            #pragma unroll
            for (int nt = 0; nt < 8; nt++) {
                #pragma unroll
                for (int c = 0; c < 2; c++)
                    wv[nt * 2 + c] =
                        g_winv[classBase + wn * 64 + nt * 8 + ql * 2 + c];
            }
            #pragma unroll
            for (int mt = 0; mt < 2; mt++) {
                #pragma unroll
                for (int h = 0; h < 2; h++) {
                    const int   rloc = wm * 32 + mt * 16 + qid + h * 8;
                    const float ew   = g_einv[rowBase + rloc] * L2E_64;
                    float sum = 0.f;
                    #pragma unroll
                    for (int j = 0; j < 16; j++) {
                        float u = acc[mt][j >> 1][h * 2 + (j & 1)] * ew;
                        sum += ex2(fmaf(u, wv[j], -L2E_64));
                    }
                    sum += __shfl_xor_sync(0xffffffffu, sum, 1);
                    sum += __shfl_xor_sync(0xffffffffu, sum, 2);
                    if (ql == 0)
                        g_psum[(size_t)(rowBase + rloc) * NTE + tileIdx] = sum;
                }
            }
            #pragma unroll
            for (int mt = 0; mt < 2; mt++)
                #pragma unroll
                for (int nt = 0; nt < 8; nt++)
                    #pragma unroll
                    for (int c = 0; c < 4; c++) acc[mt][nt][c] = 0.f;
        }

        // rotate stage bases by 2 (8 chunks consumed, 8 mod 3 == 2)
        {
            uint32_t t0 = pst[0], t1 = pst[1];
            pst[0] = pst[2];
            pst[1] = t0;
            pst[2] = t1;
        }
    }
}

// ---------------------------------------------------------------------------
// Finalize stage 1: one warp per row -- sums NTE partials, computes the exact
// fp32 label dot (label_dot folded in), applies the margin correction.
// ---------------------------------------------------------------------------
__global__ void finalize_rows_kernel(const float* __restrict__ E,
                                     const float* __restrict__ W,
                                     const int* __restrict__ labels) {
    int gw   = (blockIdx.x * blockDim.x + threadIdx.x) >> 5;
    int lane = threadIdx.x & 31;
    if (gw >= B) return;

    const float* ps = g_psum + (size_t)gw * NTE;
    float s = 0.f;
    for (int t = lane; t < NTE; t += 32) s += ps[t];

    int lab = labels[gw];
    const float* e = E + (size_t)gw * D;
    const float* w = W + (size_t)lab * D;
    float dot = 0.f, ws = 0.f;
    #pragma unroll
    for (int i = 0; i < D / 32; i++) {
        float wv = w[lane + i * 32];
        dot = fmaf(e[lane + i * 32], wv, dot);
        ws  = fmaf(wv, wv, ws);
    }
    #pragma unroll
    for (int o = 16; o > 0; o >>= 1) {
        s   += __shfl_xor_sync(0xffffffffu, s, o);
        dot += __shfl_xor_sync(0xffffffffu, dot, o);
        ws  += __shfl_xor_sync(0xffffffffu, ws, o);
    }

    if (lane == 0) {
        float winv = 1.0f / fmaxf(sqrtf(ws), 1e-12f);
        float cosl = dot * g_einv[gw] * winv;
        float c2   = 1.0f - cosl * cosl;
        float sine = sqrtf(fminf(fmaxf(c2, 0.f), 1.f));
        float phi  = cosl * COS_M - sine * SIN_M;
        phi = (cosl > TH_M) ? phi : (cosl - MM_M);

        float lo = SCALE_F * cosl;   // original label logit
        float ln = SCALE_F * phi;    // margined logit
        s += expf(ln - SCALE_F) - expf(lo - SCALE_F);
        // logZ = 64 + log(s); nll = logZ - ln
        g_nll[gw] = SCALE_F + logf(s) - ln;
    }
}

__global__ void finalize_reduce_kernel(float* __restrict__ out) {
    __shared__ float red[B];
    int b = threadIdx.x;
    red[b] = g_nll[b];
    __syncthreads();
    #pragma unroll
    for (int o = B / 2; o > 0; o >>= 1) {
        if (b < o) red[b] += red[b + o];
        __syncthreads();
    }
    if (b == 0) out[0] = red[0] / (float)B;
}

// ---------------------------------------------------------------------------
extern "C" void kernel_launch(void* const* d_in, const int* in_sizes, int n_in,
                              void* d_out, int out_size) {
    const float* E      = (const float*)d_in[0];
    const float* W      = (const float*)d_in[1];
    const int*   labels = (const int*)d_in[2];
    float*       out    = (float*)d_out;

    cudaFuncSetAttribute(gemm_tc_kernel,
                         cudaFuncAttributeMaxDynamicSharedMemorySize, SMEM_BYTES);

    e_conv_kernel<<<(B * 32) / 256, 256>>>(E);
    w_conv_kernel<<<(C * 32 + 255) / 256, 256>>>(W);

    gemm_tc_kernel<<<GRIDP, 256, SMEM_BYTES>>>();

    finalize_rows_kernel<<<(B * 32 + 255) / 256, 256>>>(E, W, labels);
    finalize_reduce_kernel<<<1, B>>>(out);
}

// round 17
// speedup vs baseline: 1.1131x; 1.1131x over previous
#include <cuda_runtime.h>
#include <cuda_fp16.h>
#include <math.h>
#include <stdint.h>

// ---------------------------------------------------------------------------
// Problem constants
// ---------------------------------------------------------------------------
#define B       1024
#define D       512
#define C       100000
#define TM      128                    // CTA tile rows
#define TN      128                    // CTA tile classes
#define NT      ((C + TN - 1) / TN)    // 782 class tiles
#define NTE     (NT * 2)               // 2 col-half partials per class tile
#define KCHUNK  64                     // fp16 K elems per chunk (128B rows)
#define NCHUNK  (D / KCHUNK)           // 8
#define SCALE_F 64.0f
#define L2E_64  92.33248261689366f     // 64 * log2(e)

// ArcFace margin constants (margin = 0.5)
#define COS_M  0.8775825618903728f
#define SIN_M  0.47942553860420301f
#define TH_M  (-0.8775825618903728f)
#define MM_M   0.23971276930210151f

// smem: per stage A tile 128x128B (16KB) + B tile 128x128B (16KB)
#define TILE_BYTES  16384
#define STAGE_BYTES (2 * TILE_BYTES)
#define SMEM_BYTES  (3 * STAGE_BYTES)      // 98304 -> 2 CTA/SM

// Scratch (__device__ globals; no allocations allowed).
// g_Eh / g_Wh hold PRE-NORMALIZED rows (x / ||x||) in fp16, so the MMA
// accumulator is directly the cosine similarity.
__device__ __half g_Eh[(size_t)B * D];
__device__ __half g_Wh[(size_t)C * D];
__device__ float  g_einv[B];           // 1/||e|| (fp32, for the exact label path)
__device__ float  g_psum[(size_t)B * NTE];
__device__ float  g_nll[B];

// ---------------------------------------------------------------------------
// PTX helpers (base ISA only -- nothing gated on sm_103a)
// ---------------------------------------------------------------------------
__device__ __forceinline__ uint32_t smem_u32(const void* p) {
    uint32_t a;
    asm("{ .reg .u64 t; cvta.to.shared.u64 t, %1; cvt.u32.u64 %0, t; }"
        : "=r"(a) : "l"(p));
    return a;
}
__device__ __forceinline__ void cp16(uint32_t dst, const void* src) {
    asm volatile("cp.async.cg.shared.global [%0], [%1], 16;"
                 :: "r"(dst), "l"(src));
}
__device__ __forceinline__ void cp_commit() {
    asm volatile("cp.async.commit_group;" ::: "memory");
}
template <int N> __device__ __forceinline__ void cp_wait() {
    asm volatile("cp.async.wait_group %0;" :: "n"(N) : "memory");
}
__device__ __forceinline__ void st_zero16(uint32_t dst) {
    asm volatile("st.shared.v4.u32 [%0], {%1, %1, %1, %1};"
                 :: "r"(dst), "r"(0u) : "memory");
}
__device__ __forceinline__ void ldsm4(uint32_t* r, uint32_t addr) {
    asm volatile("ldmatrix.sync.aligned.m8n8.x4.shared.b16 {%0,%1,%2,%3}, [%4];"
                 : "=r"(r[0]), "=r"(r[1]), "=r"(r[2]), "=r"(r[3]) : "r"(addr));
}
__device__ __forceinline__ void mma_f16(float* d, const uint32_t* a,
                                        const uint32_t* b) {
    asm volatile(
        "mma.sync.aligned.m16n8k16.row.col.f32.f16.f16.f32 "
        "{%0,%1,%2,%3}, {%4,%5,%6,%7}, {%8,%9}, {%0,%1,%2,%3};"
        : "+f"(d[0]), "+f"(d[1]), "+f"(d[2]), "+f"(d[3])
        : "r"(a[0]), "r"(a[1]), "r"(a[2]), "r"(a[3]), "r"(b[0]), "r"(b[1]));
}
__device__ __forceinline__ float ex2(float x) {
    float r;
    asm("ex2.approx.ftz.f32 %0, %1;" : "=f"(r) : "f"(x));
    return r;
}

// ---------------------------------------------------------------------------
// Fused conv kernel: one warp per row over C+B rows. Computes 1/||x|| in
// fp32, writes the NORMALIZED row (x * inv) as fp16. Rows [0, C) -> W,
// rows [C, C+B) -> E (also records g_einv for the exact label path).
// ---------------------------------------------------------------------------
__global__ void conv_kernel(const float* __restrict__ E,
                            const float* __restrict__ W) {
    int row  = (blockIdx.x * blockDim.x + threadIdx.x) >> 5;
    int lane = threadIdx.x & 31;
    if (row >= C + B) return;
    const bool  isE = (row >= C);
    const int   r   = isE ? row - C : row;
    const float* src = isE ? (E + (size_t)r * D) : (W + (size_t)r * D);
    __half2*     dst = isE ? (__half2*)(g_Eh + (size_t)r * D)
                           : (__half2*)(g_Wh + (size_t)r * D);
    float4 v[4];
    float ss = 0.f;
    #pragma unroll
    for (int j = 0; j < 4; j++) {
        v[j] = *(const float4*)(src + (j * 32 + lane) * 4);
        ss = fmaf(v[j].x, v[j].x, fmaf(v[j].y, v[j].y,
             fmaf(v[j].z, v[j].z, fmaf(v[j].w, v[j].w, ss))));
    }
    #pragma unroll
    for (int o = 16; o > 0; o >>= 1) ss += __shfl_xor_sync(0xffffffffu, ss, o);
    float inv = 1.0f / fmaxf(sqrtf(ss), 1e-12f);
    #pragma unroll
    for (int j = 0; j < 4; j++) {
        dst[(j * 32 + lane) * 2]     = __floats2half2_rn(v[j].x * inv, v[j].y * inv);
        dst[(j * 32 + lane) * 2 + 1] = __floats2half2_rn(v[j].z * inv, v[j].w * inv);
    }
    if (isE && lane == 0) g_einv[r] = inv;
}

// ---------------------------------------------------------------------------
// Main: fp16 mma.sync GEMM on pre-normalized operands (acc == cosine).
// 128x128 CTA tile, 256 threads / 8 warps of 32x64 (4 warps per SMSP),
// 3-stage cp.async pipeline, one __syncthreads per chunk. Epilogue:
// partial sums  sum_j exp2(cos_j*K - K), K = 64*log2(e)  (fixed max 64).
// grid (8, 782) x-major: W tile HBM-read once, L2-hit by the other 7 rowTiles.
// ---------------------------------------------------------------------------
__global__ void __launch_bounds__(256, 2)
gemm_tc_kernel(void) {
    extern __shared__ char sdata[];

    const int tid  = threadIdx.x;
    const int wid  = tid >> 5;
    const int lane = tid & 31;
    const int wm   = wid >> 1;         // 0..3 : 32-row slice
    const int wn   = wid & 1;          // 0..1 : 64-col half
    const int qid  = lane >> 2;        // 0..7
    const int ql   = lane & 3;         // 0..3
    const int rowBase   = blockIdx.x * TM;
    const int classBase = blockIdx.y * TN;

    float acc[2][8][4];
    #pragma unroll
    for (int mt = 0; mt < 2; mt++)
        #pragma unroll
        for (int nt = 0; nt < 8; nt++)
            #pragma unroll
            for (int c = 0; c < 4; c++) acc[mt][nt][c] = 0.f;

    const uint32_t s0 = smem_u32(sdata);

    // --- chunk loader: A 16KB + B 16KB, XOR-swizzled 16B units, 4+4/thread ---
    auto load_chunk = [&](int k, int st) {
        const uint32_t sa  = s0 + st * STAGE_BYTES;
        const uint32_t sb  = sa + TILE_BYTES;
        const int      kof = k * KCHUNK;
        const __half*  Ep  = g_Eh + (size_t)rowBase * D + kof;
        #pragma unroll
        for (int i = 0; i < 4; i++) {
            int idx = tid + i * 256;           // 0..1023
            int r = idx >> 3, c = idx & 7;
            uint32_t dst = sa + r * 128 + ((c ^ (r & 7)) << 4);
            cp16(dst, Ep + (size_t)r * D + c * 8);
        }
        #pragma unroll
        for (int i = 0; i < 4; i++) {
            int idx = tid + i * 256;
            int r = idx >> 3, c = idx & 7;
            int cls = classBase + r;
            uint32_t dst = sb + r * 128 + ((c ^ (r & 7)) << 4);
            if (cls < C) cp16(dst, g_Wh + (size_t)cls * D + kof + c * 8);
            else         st_zero16(dst);       // zero row -> term 2^-92 ~ 0
        }
        cp_commit();
    };

    // ldmatrix per-lane address components
    const int aRow = (lane & 7) + ((lane >> 3) & 1) * 8;   // row within 16
    const int kgA  = lane >> 4;                            // k half
    const int bRow = (lane & 7) + (lane >> 4) * 8;         // row within 16
    const int kgB  = (lane >> 3) & 1;

    auto compute_chunk = [&](int st) {
        const uint32_t sa = s0 + st * STAGE_BYTES;
        const uint32_t sb = sa + TILE_BYTES;
        #pragma unroll
        for (int ks = 0; ks < 4; ks++) {
            uint32_t a[2][4], bb[4][4];
            const int cA = ks * 2 + kgA;
            const int cB = ks * 2 + kgB;
            const uint32_t swA = (uint32_t)((cA ^ (lane & 7)) << 4);
            const uint32_t swB = (uint32_t)((cB ^ (lane & 7)) << 4);
            #pragma unroll
            for (int mt = 0; mt < 2; mt++)
                ldsm4(a[mt], sa + (wm * 32 + mt * 16 + aRow) * 128 + swA);
            #pragma unroll
            for (int ntp = 0; ntp < 4; ntp++)
                ldsm4(bb[ntp], sb + (wn * 64 + ntp * 16 + bRow) * 128 + swB);
            #pragma unroll
            for (int mt = 0; mt < 2; mt++)
                #pragma unroll
                for (int nt = 0; nt < 8; nt++) {
                    uint32_t bfrag[2] = { bb[nt >> 1][(nt & 1) * 2],
                                          bb[nt >> 1][(nt & 1) * 2 + 1] };
                    mma_f16(acc[mt][nt], a[mt], bfrag);
                }
        }
    };

    // prologue: 2 chunks in flight, one stage left empty
    load_chunk(0, 0);
    load_chunk(1, 1);

    for (int k = 0; k < NCHUNK; k++) {
        if (k < NCHUNK - 1) cp_wait<1>();   // chunk k landed (k+1 may fly)
        else                cp_wait<0>();
        __syncthreads();                    // all warps done with chunk k-1's stage
        if (k + 2 < NCHUNK) load_chunk(k + 2, (k + 2) % 3);
        compute_chunk(k % 3);
    }

    // --- epilogue: acc == cosine; partial Σ exp2(cos*K - K), K = 64*log2e ---
    const int tileIdx = blockIdx.y * 2 + wn;
    #pragma unroll
    for (int mt = 0; mt < 2; mt++) {
        #pragma unroll
        for (int h = 0; h < 2; h++) {
            const int rloc = wm * 32 + mt * 16 + qid + h * 8;
            float s = 0.f;
            #pragma unroll
            for (int j = 0; j < 16; j++) {
                float cv = acc[mt][j >> 1][h * 2 + (j & 1)];
                s += ex2(fmaf(cv, L2E_64, -L2E_64));
            }
            s += __shfl_xor_sync(0xffffffffu, s, 1);
            s += __shfl_xor_sync(0xffffffffu, s, 2);
            if (ql == 0)
                g_psum[(size_t)(rowBase + rloc) * NTE + tileIdx] = s;
        }
    }
}

// ---------------------------------------------------------------------------
// Finalize stage 1: one warp per row -- sums NTE partials, computes the exact
// fp32 label dot + weight norm inline, applies the margin correction.
// ---------------------------------------------------------------------------
__global__ void finalize_rows_kernel(const float* __restrict__ E,
                                     const float* __restrict__ W,
                                     const int* __restrict__ labels) {
    int gw   = (blockIdx.x * blockDim.x + threadIdx.x) >> 5;
    int lane = threadIdx.x & 31;
    if (gw >= B) return;

    const float* ps = g_psum + (size_t)gw * NTE;
    float s = 0.f;
    for (int t = lane; t < NTE; t += 32) s += ps[t];

    int lab = labels[gw];
    const float* e = E + (size_t)gw * D;
    const float* w = W + (size_t)lab * D;
    float dot = 0.f, ws = 0.f;
    #pragma unroll
    for (int i = 0; i < D / 32; i++) {
        float wv = w[lane + i * 32];
        dot = fmaf(e[lane + i * 32], wv, dot);
        ws  = fmaf(wv, wv, ws);
    }
    #pragma unroll
    for (int o = 16; o > 0; o >>= 1) {
        s   += __shfl_xor_sync(0xffffffffu, s, o);
        dot += __shfl_xor_sync(0xffffffffu, dot, o);
        ws  += __shfl_xor_sync(0xffffffffu, ws, o);
    }

    if (lane == 0) {
        float winv = 1.0f / fmaxf(sqrtf(ws), 1e-12f);
        float cosl = dot * g_einv[gw] * winv;
        float c2   = 1.0f - cosl * cosl;
        float sine = sqrtf(fminf(fmaxf(c2, 0.f), 1.f));
        float phi  = cosl * COS_M - sine * SIN_M;
        phi = (cosl > TH_M) ? phi : (cosl - MM_M);

        float lo = SCALE_F * cosl;   // original label logit
        float ln = SCALE_F * phi;    // margined logit
        s += expf(ln - SCALE_F) - expf(lo - SCALE_F);
        // logZ = 64 + log(s); nll = logZ - ln
        g_nll[gw] = SCALE_F + logf(s) - ln;
    }
}

__global__ void finalize_reduce_kernel(float* __restrict__ out) {
    __shared__ float red[B];
    int b = threadIdx.x;
    red[b] = g_nll[b];
    __syncthreads();
    #pragma unroll
    for (int o = B / 2; o > 0; o >>= 1) {
        if (b < o) red[b] += red[b + o];
        __syncthreads();
    }
    if (b == 0) out[0] = red[0] / (float)B;
}

// ---------------------------------------------------------------------------
extern "C" void kernel_launch(void* const* d_in, const int* in_sizes, int n_in,
                              void* d_out, int out_size) {
    const float* E      = (const float*)d_in[0];
    const float* W      = (const float*)d_in[1];
    const int*   labels = (const int*)d_in[2];
    float*       out    = (float*)d_out;

    cudaFuncSetAttribute(gemm_tc_kernel,
                         cudaFuncAttributeMaxDynamicSharedMemorySize, SMEM_BYTES);

    conv_kernel<<<((C + B) * 32 + 255) / 256, 256>>>(E, W);

    dim3 grid(B / TM, NT);   // (8, 782), x-major => W-tile L2 reuse
    gemm_tc_kernel<<<grid, 256, SMEM_BYTES>>>();

    finalize_rows_kernel<<<(B * 32 + 255) / 256, 256>>>(E, W, labels);
    finalize_reduce_kernel<<<1, B>>>(out);
}